// round 3
// baseline (speedup 1.0000x reference)
#include <cuda_runtime.h>
#include <cstdint>
#include <math.h>

// IMLE sampler: out[s,b,n] = 1 iff (logits[b,n] + Gumbel(noise[s,b,n])) is in
// the row's top-k.  S=16, B=128, N=16384, k=32.
//
// v3: selection on w = log2(u) * E,  E = -ln2*exp(-logit)  (w >= 0, monotone
// decreasing in the perturbed logit => top-k largest == k smallest w).
//  - lean hot loop: 2 LDG + 4 MUFU + 4 FMUL + 4 FMIN + STS + STG per float4
//  - NO guard logic: threshold carries multiplicative (x1.29) AND absolute
//    (+2e-3) slack, provably covering worst-case __log2f error (<=1.3e-4 abs
//    on w for |logit|<=8) -- exact top-k always inside the candidate set.
//  - t* = max over 32 warp-slices of slice-min(w): >=32 elements <= t*.
//  - candidates exactly recomputed with double log, ranked O(c^2),
//    lowest-index tie-break (matches jax.lax.top_k). rel_err == 0 so far.

#define NCOLS   16384
#define THREADS 1024
#define CHUNKS  4            // 4 float4 per thread = 16 elements
#define CAP     2048
#define MAXLROWS 128

__device__ float g_E[MAXLROWS * NCOLS];   // -ln2 * exp(-logit)

__global__ void precompute_E(const float* __restrict__ logits, int n) {
    int i = blockIdx.x * blockDim.x + threadIdx.x;
    if (i < n) g_E[i] = -0.6931471805599453f * __expf(-logits[i]);
}

// float32 log chain, correctly rounded via double (immune to fast-math):
// t1=log(u); t3=log(-t1); p = logit - t3   (matches reference op-by-op)
__device__ __forceinline__ float exact_perturb(float u, float lg) {
    float t1 = (float)log((double)u);
    float t3 = (float)log((double)(-t1));
    return lg + (-t3);
}

extern __shared__ char dynsmem[];

__global__ __launch_bounds__(THREADS, 2)
void imle_topk_kernel(const float* __restrict__ logits,
                      const float* __restrict__ noise,
                      const int* __restrict__ kptr,
                      float* __restrict__ out,
                      int Brows)
{
    float* shw  = (float*)dynsmem;                          // [NCOLS] keys
    int*   cidx = (int*)(dynsmem + NCOLS * 4);              // [CAP]
    float* cval = (float*)(dynsmem + NCOLS * 4 + CAP * 4);  // [CAP]
    __shared__ float wmin_s[32];
    __shared__ float sh_thr;
    __shared__ int   sh_cnt;

    const int tid  = threadIdx.x;
    const int lane = tid & 31;
    const int warp = tid >> 5;
    const int row  = blockIdx.x;
    const size_t rowoff = (size_t)row * NCOLS;
    const size_t logoff = (size_t)(row % Brows) * NCOLS;

    const float4* n4 = reinterpret_cast<const float4*>(noise + rowoff);
    const float4* e4 = reinterpret_cast<const float4*>(g_E + logoff);
    float4*       o4 = reinterpret_cast<float4*>(out + rowoff);
    float4*       w4 = reinterpret_cast<float4*>(shw);

    if (tid == 0) sh_cnt = 0;

    // ---- Phase 1: stream noise -> w keys -> smem; zero output; warp-min ----
    float mymin = INFINITY;
    const float4 z4 = make_float4(0.f, 0.f, 0.f, 0.f);
    #pragma unroll
    for (int c = 0; c < CHUNKS; ++c) {
        int v = tid + c * THREADS;           // float4 index in row
        float4 u = __ldcs(&n4[v]);           // streaming: read once
        float4 E = __ldg(&e4[v]);            // L2-resident across S samples
        float4 w;
        w.x = __log2f(u.x) * E.x;            // = (-ln u)*exp(-logit) >= 0
        w.y = __log2f(u.y) * E.y;
        w.z = __log2f(u.z) * E.z;
        w.w = __log2f(u.w) * E.w;
        w4[v] = w;
        mymin = fminf(mymin,
                      fminf(fminf(w.x, w.y), fminf(w.z, w.w)));
        __stcs(&o4[v], z4);
    }

    // ---- Phase 2: t* = max over warps of per-warp min; add safety slack ----
    #pragma unroll
    for (int off = 16; off > 0; off >>= 1)
        mymin = fminf(mymin, __shfl_xor_sync(0xFFFFFFFFu, mymin, off));
    if (lane == 0) wmin_s[warp] = mymin;
    __syncthreads();
    if (warp == 0) {
        float m = wmin_s[lane];
        #pragma unroll
        for (int off = 16; off > 0; off >>= 1)
            m = fmaxf(m, __shfl_xor_sync(0xFFFFFFFFu, m, off));
        if (lane == 0) sh_thr = m * 1.29f + 2e-3f;   // covers fast-log error
    }
    __syncthreads();

    int kk = kptr ? *kptr : 32;
    if (kk < 1) kk = 1;
    if (kk > NCOLS) kk = NCOLS;

    // ---- Phase 3: collect candidates (w <= thr); >=32 guaranteed ----
    float thr = sh_thr;
    #pragma unroll
    for (int c = 0; c < CHUNKS; ++c) {
        int v = tid + c * THREADS;
        float4 s = w4[v];
        if (s.x <= thr) { int p = atomicAdd(&sh_cnt, 1); if (p < CAP) cidx[p] = 4*v + 0; }
        if (s.y <= thr) { int p = atomicAdd(&sh_cnt, 1); if (p < CAP) cidx[p] = 4*v + 1; }
        if (s.z <= thr) { int p = atomicAdd(&sh_cnt, 1); if (p < CAP) cidx[p] = 4*v + 2; }
        if (s.w <= thr) { int p = atomicAdd(&sh_cnt, 1); if (p < CAP) cidx[p] = 4*v + 3; }
    }
    __syncthreads();
    int cnt = sh_cnt < CAP ? sh_cnt : CAP;

    // ---- Phase 4: exact recompute for candidates (L2-hot reloads) ----
    for (int i = tid; i < cnt; i += THREADS) {
        int idx = cidx[i];
        float u  = noise[rowoff + idx];
        float lg = logits[logoff + idx];
        cval[i] = exact_perturb(u, lg);
    }
    __syncthreads();

    // ---- Phase 5: exact O(c^2) rank, lowest-index tie-break ----
    for (int i = tid; i < cnt; i += THREADS) {
        float pi = cval[i];
        int   ii = cidx[i];
        int r = 0;
        for (int j = 0; j < cnt; ++j) {
            float pj = cval[j];
            r += (pj > pi) || (pj == pi && cidx[j] < ii);
        }
        if (r < kk) out[rowoff + ii] = 1.0f;
    }
}

extern "C" void kernel_launch(void* const* d_in, const int* in_sizes, int n_in,
                              void* d_out, int out_size) {
    // Identify inputs by size: k is the scalar, noise the largest tensor.
    int iK = -1, iU = -1, iL = -1;
    for (int i = 0; i < n_in; ++i)
        if (in_sizes[i] == 1) iK = i;
    long best = -1;
    for (int i = 0; i < n_in; ++i) {
        if (i == iK) continue;
        if ((long)in_sizes[i] > best) { best = in_sizes[i]; iU = i; }
    }
    for (int i = 0; i < n_in; ++i)
        if (i != iK && i != iU) { iL = i; break; }

    const float* logits = (const float*)d_in[iL];
    const float* noise  = (const float*)d_in[iU];
    const int*   kptr   = (iK >= 0) ? (const int*)d_in[iK] : nullptr;
    float* out = (float*)d_out;

    int rows  = in_sizes[iU] / NCOLS;   // S*B = 2048
    int Brows = in_sizes[iL] / NCOLS;   // B   = 128
    int nlog  = in_sizes[iL];
    if (Brows > MAXLROWS) Brows = MAXLROWS;
    if (nlog > MAXLROWS * NCOLS) nlog = MAXLROWS * NCOLS;

    precompute_E<<<(nlog + 255) / 256, 256>>>(logits, nlog);

    static bool attr_done = false;
    int dyn = NCOLS * 4 + CAP * 4 + CAP * 4;   // 64KB + 8KB + 8KB = 80KB
    if (!attr_done) {
        cudaFuncSetAttribute(imle_topk_kernel,
                             cudaFuncAttributeMaxDynamicSharedMemorySize, dyn);
        attr_done = true;
    }
    imle_topk_kernel<<<rows, THREADS, dyn>>>(logits, noise, kptr, out, Brows);
}

// round 4
// speedup vs baseline: 1.7630x; 1.7630x over previous
#include <cuda_runtime.h>
#include <cstdint>
#include <math.h>

// IMLE sampler: out[s,b,n] = 1 iff (logits[b,n] + Gumbel(noise[s,b,n])) is in
// the row's top-k.  S=16, B=128, N=16384, k=32.
//
// v4: 3-kernel decoupled design.
//   precompute_G: per-element candidate threshold G (data-adaptive, ~128
//                 expected candidates/row).  candidate iff __log2f(u) >= G.
//   collect:      barrier-free full-width stream: read noise (ldcs), zero
//                 out (stcs), append candidates (u,idx) to per-row lists.
//   select:       per row: fast keys -> 2-round byte radix for kth fast key
//                 -> exact double-log recompute of ~40 band survivors ->
//                 O(c^2) exact rank, lowest-index tie-break (jax top_k).
//   fallback (never fires on sane data): widening rescan inside select.

#define NCOLS    16384
#define NV4      (NCOLS/4)
#define MAXROWS  4096
#define MAXLROWS 256
#define CAP      2048
#define SURV     512
#define TARGETC  128.0f
#define DELTA    0.05f

__device__ float g_G[(size_t)MAXLROWS * NCOLS];
__device__ uint2 g_cand[(size_t)MAXROWS * CAP];
__device__ int   g_cnt[MAXROWS];

__device__ __forceinline__ unsigned f2k(float f) {
    unsigned b = __float_as_uint(f);
    return b ^ ((unsigned)((int)b >> 31) | 0x80000000u);
}
__device__ __forceinline__ float k2f(unsigned k) {
    unsigned b = (k & 0x80000000u) ? (k ^ 0x80000000u) : ~k;
    return __uint_as_float(b);
}
// float32 log chain, correctly rounded via double (immune to fast-math):
// t1=log(u); t3=log(-t1); p = logit - t3   (matches reference op-by-op)
__device__ __forceinline__ float exact_perturb(float u, float lg) {
    float t1 = (float)log((double)u);
    float t3 = (float)log((double)(-t1));
    return lg + (-t3);
}

// ---------------------------------------------------------------------------
__global__ void precompute_G(const float* __restrict__ logits,
                             int nrows, int Brows)
{
    __shared__ float red[32];
    int row = blockIdx.x;
    int tid = threadIdx.x, lane = tid & 31, warp = tid >> 5;
    const float* L = logits + (size_t)row * NCOLS;

    float s = 0.f;
    for (int i = tid; i < NCOLS; i += blockDim.x) s += __expf(L[i]);
    #pragma unroll
    for (int off = 16; off; off >>= 1) s += __shfl_xor_sync(~0u, s, off);
    if (lane == 0) red[warp] = s;
    __syncthreads();
    if (warp == 0) {
        float t = (lane < (int)(blockDim.x >> 5)) ? red[lane] : 0.f;
        #pragma unroll
        for (int off = 16; off; off >>= 1) t += __shfl_xor_sync(~0u, t, off);
        if (lane == 0) red[0] = t;
    }
    __syncthreads();
    float S = red[0];
    float C = TARGETC / S;                         // S=inf -> C=0 -> fallback
    const float INV_LN2 = 1.4426950408889634f;
    for (int i = tid; i < NCOLS; i += blockDim.x) {
        float G = -C * __expf(L[i]) * INV_LN2;     // <= 0
        g_G[(size_t)row * NCOLS + i] = G * 1.01f - 1e-6f;  // widen (safety)
    }
    int per = (nrows + Brows - 1) / Brows;
    for (int j = tid; j < per; j += blockDim.x) {
        int q = row * per + j;
        if (q < nrows) g_cnt[q] = 0;
    }
}

// ---------------------------------------------------------------------------
__global__ __launch_bounds__(256)
void collect_kernel(const float* __restrict__ noise,
                    float* __restrict__ out, int Brows)
{
    const int row = blockIdx.x, tid = threadIdx.x;
    const int lrow = row % Brows;
    const float4* n4 = reinterpret_cast<const float4*>(noise + (size_t)row * NCOLS);
    const float4* g4 = reinterpret_cast<const float4*>(g_G + (size_t)lrow * NCOLS);
    float4*       o4 = reinterpret_cast<float4*>(out + (size_t)row * NCOLS);
    const float4 z4 = make_float4(0.f, 0.f, 0.f, 0.f);

    #pragma unroll 4
    for (int c = 0; c < NV4 / 256; ++c) {
        int v = tid + c * 256;
        float4 u = __ldcs(&n4[v]);
        float4 G = __ldg(&g4[v]);
        __stcs(&o4[v], z4);
        float t0 = __log2f(u.x), t1 = __log2f(u.y);
        float t2 = __log2f(u.z), t3 = __log2f(u.w);
        if (t0 >= G.x) { int p = atomicAdd(&g_cnt[row], 1); if (p < CAP) g_cand[(size_t)row*CAP + p] = make_uint2(__float_as_uint(u.x), 4*v+0); }
        if (t1 >= G.y) { int p = atomicAdd(&g_cnt[row], 1); if (p < CAP) g_cand[(size_t)row*CAP + p] = make_uint2(__float_as_uint(u.y), 4*v+1); }
        if (t2 >= G.z) { int p = atomicAdd(&g_cnt[row], 1); if (p < CAP) g_cand[(size_t)row*CAP + p] = make_uint2(__float_as_uint(u.z), 4*v+2); }
        if (t3 >= G.w) { int p = atomicAdd(&g_cnt[row], 1); if (p < CAP) g_cand[(size_t)row*CAP + p] = make_uint2(__float_as_uint(u.w), 4*v+3); }
    }
}

// ---------------------------------------------------------------------------
__global__ __launch_bounds__(256)
void select_kernel(const float* __restrict__ noise,
                   const float* __restrict__ logits,
                   const int* __restrict__ kptr,
                   float* __restrict__ out, int Brows)
{
    __shared__ unsigned s_key[CAP];
    __shared__ unsigned hist[256];
    __shared__ float e_val[SURV];
    __shared__ int   e_idx[SURV];
    __shared__ int   s_misc[8];   // 0:b1 1:n1 2:b2 3:scnt 4:tot

    const int row = blockIdx.x, tid = threadIdx.x;
    const int lane = tid & 31, warp = tid >> 5;
    const int lrow = row % Brows;
    const size_t rowoff = (size_t)row * NCOLS;
    const size_t logoff = (size_t)lrow * NCOLS;

    int kk = kptr ? *kptr : 32;
    if (kk < 1) kk = 1;
    if (kk > NCOLS) kk = NCOLS;
    int cnt = g_cnt[row];

    if (cnt < kk || cnt > CAP) {
        // ---- fallback: widening rescan (practically unreachable) ----
        float s = 1.0f, sHi = -1.0f;
        int chosen = 0;
        for (int it = 0; it < 64 && !chosen; ++it) {
            int c = 0;
            for (int v = tid; v < NCOLS; v += 256) {
                float t = __log2f(noise[rowoff + v]);
                float g = (g_G[logoff + v] - 1e-6f) * s;
                c += (t >= g) ? 1 : 0;
            }
            #pragma unroll
            for (int off = 16; off; off >>= 1) c += __shfl_xor_sync(~0u, c, off);
            if (lane == 0) hist[warp] = (unsigned)c;
            __syncthreads();
            if (tid == 0) {
                int tot = 0;
                for (int wg = 0; wg < 8; ++wg) tot += (int)hist[wg];
                s_misc[4] = tot;
            }
            __syncthreads();
            int tot = s_misc[4];
            if (tot >= kk && (sHi < 0.f || s < sHi)) sHi = s;
            if (tot >= kk && tot <= CAP) chosen = 1;
            else if (tot < kk) s *= 4.0f;
            else s *= 0.70710678f;
            __syncthreads();
        }
        if (!chosen) s = (sHi > 0.f) ? sHi : 1e30f;
        if (tid == 0) s_misc[3] = 0;
        __syncthreads();
        for (int v = tid; v < NCOLS; v += 256) {
            float uu = noise[rowoff + v];
            float t  = __log2f(uu);
            float g  = (g_G[logoff + v] - 1e-6f) * s;
            if (t >= g) {
                int p = atomicAdd(&s_misc[3], 1);
                if (p < CAP) g_cand[(size_t)row*CAP + p] = make_uint2(__float_as_uint(uu), v);
            }
        }
        __syncthreads();
        cnt = s_misc[3];
        if (cnt > CAP) cnt = CAP;
        if (cnt == 0) return;
    }
    if (cnt > CAP) cnt = CAP;
    if (kk > cnt) kk = cnt;

    // ---- fast keys (monotone uint encoding; NaN/Inf -> max) ----
    for (int i = tid; i < cnt; i += 256) {
        uint2 cr = g_cand[(size_t)row*CAP + i];
        float u  = __uint_as_float(cr.x);
        float lg = logits[logoff + cr.y];
        float p  = lg - __logf(-__logf(u));
        s_key[i] = (p == p) ? f2k(p) : 0xFFFFFFFFu;
    }

    // ---- radix round 1: top byte ----
    hist[tid & 255] = 0;                 // blockDim==256
    __syncthreads();
    for (int i = tid; i < cnt; i += 256) atomicAdd(&hist[s_key[i] >> 24], 1u);
    __syncthreads();
    if (warp == 0) {
        int hi = 255 - lane * 8;
        unsigned part = 0;
        #pragma unroll
        for (int j = 0; j < 8; ++j) part += hist[hi - j];
        unsigned incl = part;
        #pragma unroll
        for (int off = 1; off < 32; off <<= 1) {
            unsigned v = __shfl_up_sync(~0u, incl, off);
            if (lane >= off) incl += v;
        }
        unsigned above = incl - part;
        if (above < (unsigned)kk && incl >= (unsigned)kk) {
            unsigned cum = above;
            #pragma unroll
            for (int j = 0; j < 8; ++j) {
                unsigned h = hist[hi - j];
                if (cum + h >= (unsigned)kk) { s_misc[0] = hi - j; s_misc[1] = (int)cum; break; }
                cum += h;
            }
        }
    }
    __syncthreads();
    unsigned b1 = (unsigned)s_misc[0];
    int kk2 = kk - s_misc[1];

    // ---- radix round 2: second byte among b1-prefix keys ----
    hist[tid & 255] = 0;
    __syncthreads();
    for (int i = tid; i < cnt; i += 256) {
        unsigned k = s_key[i];
        if ((k >> 24) == b1) atomicAdd(&hist[(k >> 16) & 255u], 1u);
    }
    __syncthreads();
    if (warp == 0) {
        int hi = 255 - lane * 8;
        unsigned part = 0;
        #pragma unroll
        for (int j = 0; j < 8; ++j) part += hist[hi - j];
        unsigned incl = part;
        #pragma unroll
        for (int off = 1; off < 32; off <<= 1) {
            unsigned v = __shfl_up_sync(~0u, incl, off);
            if (lane >= off) incl += v;
        }
        unsigned above = incl - part;
        if (above < (unsigned)kk2 && incl >= (unsigned)kk2) {
            unsigned cum = above;
            #pragma unroll
            for (int j = 0; j < 8; ++j) {
                unsigned h = hist[hi - j];
                if (cum + h >= (unsigned)kk2) { s_misc[2] = hi - j; break; }
                cum += h;
            }
        }
    }
    __syncthreads();
    unsigned b2 = (unsigned)s_misc[2];
    unsigned cutU = (b1 << 24) | (b2 << 16);
    float cf = k2f(cutU);
    unsigned cutAdj;
    if (!(cf == cf) || cf > 1e30f) cutAdj = cutU;       // inf/NaN region: no band
    else                           cutAdj = f2k(cf - DELTA);

    // ---- survivors: fast key >= cut - DELTA; exact recompute ----
    if (tid == 0) s_misc[3] = 0;
    __syncthreads();
    for (int i = tid; i < cnt; i += 256) {
        if (s_key[i] >= cutAdj) {
            int p = atomicAdd(&s_misc[3], 1);
            if (p < SURV) {
                uint2 cr = g_cand[(size_t)row*CAP + i];
                float u  = __uint_as_float(cr.x);
                float lg = logits[logoff + cr.y];
                e_val[p] = exact_perturb(u, lg);
                e_idx[p] = (int)cr.y;
            }
        }
    }
    __syncthreads();
    int sc = s_misc[3];
    if (sc > SURV) sc = SURV;

    // ---- exact O(sc^2) rank, lowest-index tie-break ----
    for (int i = tid; i < sc; i += 256) {
        float pi = e_val[i];
        int   ii = e_idx[i];
        int r = 0;
        for (int j = 0; j < sc; ++j) {
            float pj = e_val[j];
            r += (pj > pi) || (pj == pi && e_idx[j] < ii);
        }
        if (r < kk) out[rowoff + ii] = 1.0f;
    }
}

// ---------------------------------------------------------------------------
extern "C" void kernel_launch(void* const* d_in, const int* in_sizes, int n_in,
                              void* d_out, int out_size) {
    int iK = -1, iU = -1, iL = -1;
    for (int i = 0; i < n_in; ++i)
        if (in_sizes[i] == 1) iK = i;
    long best = -1;
    for (int i = 0; i < n_in; ++i) {
        if (i == iK) continue;
        if ((long)in_sizes[i] > best) { best = in_sizes[i]; iU = i; }
    }
    for (int i = 0; i < n_in; ++i)
        if (i != iK && i != iU) { iL = i; break; }

    const float* logits = (const float*)d_in[iL];
    const float* noise  = (const float*)d_in[iU];
    const int*   kptr   = (iK >= 0) ? (const int*)d_in[iK] : nullptr;
    float* out = (float*)d_out;

    int rows  = in_sizes[iU] / NCOLS;   // S*B = 2048
    int Brows = in_sizes[iL] / NCOLS;   // B   = 128
    if (Brows > MAXLROWS) Brows = MAXLROWS;
    if (rows  > MAXROWS)  rows  = MAXROWS;

    precompute_G<<<Brows, 256>>>(logits, rows, Brows);
    collect_kernel<<<rows, 256>>>(noise, out, Brows);
    select_kernel<<<rows, 256>>>(noise, logits, kptr, out, Brows);
}